// round 12
// baseline (speedup 1.0000x reference)
#include <cuda_runtime.h>
#include <cuda_bf16.h>

// SpikingLateralLine: B=4096 scenarios, 1024 ant + 1024 post Izhikevich neurons,
// 10 Euler steps. HBM-bound on the two noise tensors (335 MB read-once).
//
// Layout: 1 CTA per batch element, 256 threads, each thread owns 4 ant + 4 post
// neurons. Noise loaded as float4 (coalesced LDG.128, streaming/evict-first),
// software-pipelined TWO steps ahead (4 independent LDG.128 in flight per
// thread -> MLP=4 hides DRAM latency per the 577/MLP model). All Izhikevich
// state in registers. Rate means via warp shuffle + cross-warp shared reduce.

#define TPB     256
#define N_NEUR  1024
#define STEPS   10

__device__ __forceinline__ void izh_step(float& v, float& u, float& r, float I) {
    float vn = v + (0.04f * v * v + 5.0f * v + 140.0f - u + I);
    float un = u + 0.02f * (0.2f * v - u);
    bool sp = vn >= 30.0f;
    v = sp ? -65.0f : vn;
    u = sp ? (un + 8.0f) : un;
    r = 0.95f * r + (sp ? 0.05f : 0.0f);
}

__device__ __forceinline__ void izh_step4(float4& v, float4& u, float4& r,
                                          const float4& n, float I) {
    izh_step(v.x, u.x, r.x, n.x * 0.5f + I);
    izh_step(v.y, u.y, r.y, n.y * 0.5f + I);
    izh_step(v.z, u.z, r.z, n.z * 0.5f + I);
    izh_step(v.w, u.w, r.w, n.w * 0.5f + I);
}

__global__ __launch_bounds__(TPB)
void SpikingLateralLine_kernel(
    const float* __restrict__ fish_x,  const float* __restrict__ fish_y,
    const float* __restrict__ fish_h,  const float* __restrict__ pred_x,
    const float* __restrict__ pred_y,  const float* __restrict__ pred_vx,
    const float* __restrict__ pred_vy,
    const float4* __restrict__ noise_ant,   // [STEPS, B, N_NEUR/4]
    const float4* __restrict__ noise_post,  // [STEPS, B, N_NEUR/4]
    float* __restrict__ out,                // [B, 6]
    int B)
{
    const int b = blockIdx.x;
    const int t = threadIdx.x;

    // ---- per-batch scalar sensor model (cheap, computed per-thread) ----
    float dx = pred_x[b] - fish_x[b];
    float dy = pred_y[b] - fish_y[b];
    float dist = sqrtf(dx * dx + dy * dy) + 1e-6f;
    bool  ir   = dist <= 150.0f;

    float prox = ir ? fmaxf(0.0f, 1.0f - dist / 150.0f) : 0.0f;
    float dth  = atan2f(dy, dx) - fish_h[b];
    float rel  = atan2f(sinf(dth), cosf(dth));
    float vx = pred_vx[b], vy = pred_vy[b];
    float speed    = sqrtf(vx * vx + vy * vy);
    float flow_mag = ir ? fminf(1.0f, speed * prox * 0.1f) : 0.0f;
    float flow_dir = ir ? sinf(rel) : 0.0f;
    float cr       = cosf(rel);
    float frontal  = fmaxf(0.0f,  cr);
    float caudal   = fmaxf(0.0f, -cr);

    float baseA  = ir ? prox * frontal * 15.0f : 0.0f;
    float I_post = ir ? prox * caudal  * 12.0f : 0.0f;

    // thread t covers ant neurons 4t..4t+3; all on one side of the 512 split
    bool first_half = (t < (TPB / 2));
    float boost = ((flow_dir > 0.0f) == first_half) ? 1.5f : 1.0f;

    const float I_TONIC = -2.0f;
    float Ia = baseA * boost + I_TONIC;   // + 0.5*noise added per step
    float Ip = I_post + I_TONIC;

    // ---- Izhikevich state in registers ----
    float4 vA = make_float4(-65.f, -65.f, -65.f, -65.f);
    float4 uA = make_float4(-13.f, -13.f, -13.f, -13.f);
    float4 rA = make_float4(0.f, 0.f, 0.f, 0.f);
    float4 vP = vA, uP = uA;
    float4 rP = make_float4(0.f, 0.f, 0.f, 0.f);

    size_t base   = (size_t)b * (N_NEUR / 4) + t;
    size_t stride = (size_t)B * (N_NEUR / 4);

    // software pipeline, depth 2: 4 independent LDG.128 in flight per thread.
    float4 na0 = __ldcs(&noise_ant [base]);
    float4 np0 = __ldcs(&noise_post[base]);
    float4 na1 = __ldcs(&noise_ant [base + stride]);
    float4 np1 = __ldcs(&noise_post[base + stride]);

#pragma unroll
    for (int s = 0; s < STEPS; s++) {
        float4 na_cur = na0, np_cur = np0;
        na0 = na1; np0 = np1;
        if (s + 2 < STEPS) {
            na1 = __ldcs(&noise_ant [base + (size_t)(s + 2) * stride]);
            np1 = __ldcs(&noise_post[base + (size_t)(s + 2) * stride]);
        }
        izh_step4(vA, uA, rA, na_cur, Ia);
        izh_step4(vP, uP, rP, np_cur, Ip);
    }

    // ---- reduce rate means across the block ----
    float sA = (rA.x + rA.y) + (rA.z + rA.w);
    float sP = (rP.x + rP.y) + (rP.z + rP.w);
#pragma unroll
    for (int o = 16; o > 0; o >>= 1) {
        sA += __shfl_xor_sync(0xFFFFFFFFu, sA, o);
        sP += __shfl_xor_sync(0xFFFFFFFFu, sP, o);
    }

    __shared__ float shA[TPB / 32];
    __shared__ float shP[TPB / 32];
    int w = t >> 5, l = t & 31;
    if (l == 0) { shA[w] = sA; shP[w] = sP; }
    __syncthreads();

    if (t == 0) {
        float a = 0.0f, p = 0.0f;
#pragma unroll
        for (int i = 0; i < TPB / 32; i++) { a += shA[i]; p += shP[i]; }
        float* o6 = out + (size_t)b * 6;
        o6[0] = prox;
        o6[1] = flow_dir;
        o6[2] = flow_mag;
        o6[3] = a * (1.0f / (float)N_NEUR);
        o6[4] = p * (1.0f / (float)N_NEUR);
        o6[5] = ir ? dist : 999.0f;
    }
}

extern "C" void kernel_launch(void* const* d_in, const int* in_sizes, int n_in,
                              void* d_out, int out_size) {
    const float* fish_x  = (const float*)d_in[0];
    const float* fish_y  = (const float*)d_in[1];
    const float* fish_h  = (const float*)d_in[2];
    const float* pred_x  = (const float*)d_in[3];
    const float* pred_y  = (const float*)d_in[4];
    const float* pred_vx = (const float*)d_in[5];
    const float* pred_vy = (const float*)d_in[6];
    const float4* noise_ant  = (const float4*)d_in[7];
    const float4* noise_post = (const float4*)d_in[8];
    float* out = (float*)d_out;

    int B = in_sizes[0];

    SpikingLateralLine_kernel<<<B, TPB>>>(
        fish_x, fish_y, fish_h, pred_x, pred_y, pred_vx, pred_vy,
        noise_ant, noise_post, out, B);
}

// round 17
// speedup vs baseline: 1.0734x; 1.0734x over previous
#include <cuda_runtime.h>
#include <cuda_bf16.h>

// SpikingLateralLine, round 13: instruction-reduction round.
// R12 profile: dur 64.5us, dram 62.9%, fma 41.3%, alu 29.3%, issue 63.2%, occ 46.9%.
// Math issue pressure delays load issue -> DRAM stuck at 63%. Changes:
//  - packed f32x2 v/u updates (negated-u trick), PTX fma/mul/add.rn.f32x2
//  - weighted spike-rate accumulation (replaces EMA: 1 cond-add vs FFMA+FSEL)
//  - atan2-free sensor model: sin/cos(angle-heading) expanded from dx,dy,1/dist
//  - compile-time BATCH stride -> constant address offsets
//  - pipeline depth 1 (keeps regs <=64 with packed-constant pairs)

#define TPB     256
#define N_NEUR  1024
#define STEPS   10
#define BATCH   4096

typedef unsigned long long u64;

__device__ __forceinline__ u64 pack2(float lo, float hi) {
    u64 d; asm("mov.b64 %0, {%1, %2};" : "=l"(d) : "f"(lo), "f"(hi)); return d;
}
__device__ __forceinline__ void unpack2(u64 d, float& lo, float& hi) {
    asm("mov.b64 {%0, %1}, %2;" : "=f"(lo), "=f"(hi) : "l"(d));
}
__device__ __forceinline__ u64 fma2(u64 a, u64 b, u64 c) {
    u64 d; asm("fma.rn.f32x2 %0, %1, %2, %3;" : "=l"(d) : "l"(a), "l"(b), "l"(c)); return d;
}
__device__ __forceinline__ u64 mul2(u64 a, u64 b) {
    u64 d; asm("mul.rn.f32x2 %0, %1, %2;" : "=l"(d) : "l"(a), "l"(b)); return d;
}
__device__ __forceinline__ u64 add2(u64 a, u64 b) {
    u64 d; asm("add.rn.f32x2 %0, %1, %2;" : "=l"(d) : "l"(a), "l"(b)); return d;
}

// One Euler step for a packed pair of neurons. nu2 holds -u.
// vn = 0.04 v^2 + 6 v + (140 + 0.5 n + I_drive - u); C2 = I_drive + 140 (pair).
__device__ __forceinline__ void izh_pair(
    u64& v2, u64& nu2, float& r0, float& r1,
    float n0, float n1, u64 C2, float w,
    u64 HALF2, u64 SIX2, u64 P004, u64 N0004, u64 P098)
{
    u64 n2  = pack2(n0, n1);
    u64 s2  = fma2(n2, HALF2, C2);                  // 0.5n + I + 140
    s2      = add2(s2, nu2);                         // ... - u
    u64 t2  = mul2(v2, v2);
    u64 vn2 = fma2(t2, P004, fma2(v2, SIX2, s2));
    u64 nn2 = fma2(v2, N0004, mul2(nu2, P098));      // -u_new = 0.98(-u) - 0.004v
    float vn0, vn1, nn0, nn1;
    unpack2(vn2, vn0, vn1);
    unpack2(nn2, nn0, nn1);
    bool s0 = vn0 >= 30.0f, s1 = vn1 >= 30.0f;
    float v0 = s0 ? -65.0f : vn0;
    float v1 = s1 ? -65.0f : vn1;
    float u0 = s0 ? nn0 - 8.0f : nn0;                // -(u+8) = nu - 8
    float u1 = s1 ? nn1 - 8.0f : nn1;
    r0 = s0 ? r0 + w : r0;
    r1 = s1 ? r1 + w : r1;
    v2  = pack2(v0, v1);
    nu2 = pack2(u0, u1);
}

__global__ __launch_bounds__(TPB)
void SpikingLateralLine_kernel(
    const float* __restrict__ fish_x,  const float* __restrict__ fish_y,
    const float* __restrict__ fish_h,  const float* __restrict__ pred_x,
    const float* __restrict__ pred_y,  const float* __restrict__ pred_vx,
    const float* __restrict__ pred_vy,
    const float4* __restrict__ noise_ant,   // [STEPS, BATCH, N_NEUR/4]
    const float4* __restrict__ noise_post,  // [STEPS, BATCH, N_NEUR/4]
    float* __restrict__ out)                // [BATCH, 6]
{
    const int b = blockIdx.x;
    const int t = threadIdx.x;

    // ---- sensor model, atan2-free ----
    // rel = atan2(sin(th-h), cos(th-h)) is only used via sin(rel), cos(rel),
    // which equal sin(th-h), cos(th-h); expand with sin th = dy/dist, cos th = dx/dist.
    float dx = pred_x[b] - fish_x[b];
    float dy = pred_y[b] - fish_y[b];
    float dist = sqrtf(dx * dx + dy * dy) + 1e-6f;
    bool  ir   = dist <= 150.0f;

    float prox = ir ? fmaxf(0.0f, 1.0f - dist * (1.0f / 150.0f)) : 0.0f;
    float h  = fish_h[b];
    float sh = sinf(h), ch = cosf(h);
    float rinv  = 1.0f / dist;
    float sin_d = (dy * ch - dx * sh) * rinv;   // sin(angle_to - heading)
    float cos_d = (dx * ch + dy * sh) * rinv;   // cos(angle_to - heading)

    float vx = pred_vx[b], vy = pred_vy[b];
    float speed    = sqrtf(vx * vx + vy * vy);
    float flow_mag = ir ? fminf(1.0f, speed * prox * 0.1f) : 0.0f;
    float flow_dir = ir ? sin_d : 0.0f;
    float frontal  = fmaxf(0.0f,  cos_d);
    float caudal   = fmaxf(0.0f, -cos_d);

    float baseA  = ir ? prox * frontal * 15.0f : 0.0f;
    float I_post = ir ? prox * caudal  * 12.0f : 0.0f;

    bool first_half = (t < (TPB / 2));      // neurons 4t..4t+3 all on one side of 512
    float boost = ((flow_dir > 0.0f) == first_half) ? 1.5f : 1.0f;

    float Ca = baseA * boost - 2.0f + 140.0f;   // I_ant + I_tonic + 140
    float Cp = I_post       - 2.0f + 140.0f;    // I_post + I_tonic + 140

    // ---- packed constants (register pairs) ----
    const u64 HALF2 = pack2(0.5f, 0.5f);
    const u64 SIX2  = pack2(6.0f, 6.0f);
    const u64 P004  = pack2(0.04f, 0.04f);
    const u64 N0004 = pack2(-0.004f, -0.004f);
    const u64 P098  = pack2(0.98f, 0.98f);
    const u64 CA2   = pack2(Ca, Ca);
    const u64 CP2   = pack2(Cp, Cp);

    // ---- state: v packed, nu = -u packed, spike-weight accumulators scalar ----
    u64 vA0 = pack2(-65.f, -65.f), vA1 = vA0, vP0 = vA0, vP1 = vA0;
    u64 nA0 = pack2(13.f, 13.f),   nA1 = nA0, nP0 = nA0, nP1 = nA0;
    float rA0 = 0.f, rA1 = 0.f, rA2 = 0.f, rA3 = 0.f;
    float rP0 = 0.f, rP1 = 0.f, rP2 = 0.f, rP3 = 0.f;

    // EMA r_10 = sum_s 0.05 * 0.95^(9-s) * spike_s  (exact closed form)
    const float W[STEPS] = {
        0.05f * 0.63024941f, 0.05f * 0.66342043f, 0.05f * 0.69833730f,
        0.05f * 0.73509189f, 0.05f * 0.77378094f, 0.05f * 0.81450625f,
        0.05f * 0.85737500f, 0.05f * 0.90250000f, 0.05f * 0.95000000f,
        0.05f * 1.00000000f };

    const unsigned idx = (unsigned)(b * (N_NEUR / 4) + t);
    const float4* pa = noise_ant  + idx;
    const float4* pp = noise_post + idx;
    constexpr size_t STR = (size_t)BATCH * (N_NEUR / 4);  // compile-time stride

    float4 na = __ldcs(pa);
    float4 np = __ldcs(pp);

#pragma unroll
    for (int s = 0; s < STEPS; s++) {
        float4 ca = na, cp = np;
        if (s + 1 < STEPS) {
            na = __ldcs(pa + (size_t)(s + 1) * STR);
            np = __ldcs(pp + (size_t)(s + 1) * STR);
        }
        const float w = W[s];
        izh_pair(vA0, nA0, rA0, rA1, ca.x, ca.y, CA2, w, HALF2, SIX2, P004, N0004, P098);
        izh_pair(vA1, nA1, rA2, rA3, ca.z, ca.w, CA2, w, HALF2, SIX2, P004, N0004, P098);
        izh_pair(vP0, nP0, rP0, rP1, cp.x, cp.y, CP2, w, HALF2, SIX2, P004, N0004, P098);
        izh_pair(vP1, nP1, rP2, rP3, cp.z, cp.w, CP2, w, HALF2, SIX2, P004, N0004, P098);
    }

    // ---- reduce rate means across the block ----
    float sA = (rA0 + rA1) + (rA2 + rA3);
    float sP = (rP0 + rP1) + (rP2 + rP3);
#pragma unroll
    for (int o = 16; o > 0; o >>= 1) {
        sA += __shfl_xor_sync(0xFFFFFFFFu, sA, o);
        sP += __shfl_xor_sync(0xFFFFFFFFu, sP, o);
    }

    __shared__ float shA[TPB / 32];
    __shared__ float shP[TPB / 32];
    int w = t >> 5, l = t & 31;
    if (l == 0) { shA[w] = sA; shP[w] = sP; }
    __syncthreads();

    if (t == 0) {
        float a = 0.0f, p = 0.0f;
#pragma unroll
        for (int i = 0; i < TPB / 32; i++) { a += shA[i]; p += shP[i]; }
        float* o6 = out + (size_t)b * 6;
        o6[0] = prox;
        o6[1] = flow_dir;
        o6[2] = flow_mag;
        o6[3] = a * (1.0f / (float)N_NEUR);
        o6[4] = p * (1.0f / (float)N_NEUR);
        o6[5] = ir ? dist : 999.0f;
    }
}

extern "C" void kernel_launch(void* const* d_in, const int* in_sizes, int n_in,
                              void* d_out, int out_size) {
    const float* fish_x  = (const float*)d_in[0];
    const float* fish_y  = (const float*)d_in[1];
    const float* fish_h  = (const float*)d_in[2];
    const float* pred_x  = (const float*)d_in[3];
    const float* pred_y  = (const float*)d_in[4];
    const float* pred_vx = (const float*)d_in[5];
    const float* pred_vy = (const float*)d_in[6];
    const float4* noise_ant  = (const float4*)d_in[7];
    const float4* noise_post = (const float4*)d_in[8];
    float* out = (float*)d_out;

    SpikingLateralLine_kernel<<<BATCH, TPB>>>(
        fish_x, fish_y, fish_h, pred_x, pred_y, pred_vx, pred_vy,
        noise_ant, noise_post, out);
}